// round 3
// baseline (speedup 1.0000x reference)
#include <cuda_runtime.h>

#define BB 4096
#define TT 64
#define T1 65
#define HH 64
#define PP 50
#define VV 32
#define BT 16
#define NBLK (BB / BT) /* 256 */

#define SMEM_FLOATS 24608
#define SMEM_BYTES (SMEM_FLOATS * 4)

// scratch (device globals; no allocation allowed)
__device__ float g_table[3 * 32 * 64];      // emb-part of x-projections, per gate/char
__device__ float g_phonb[3 * BB * 64];      // phon-part + both biases, per gate/batch
__device__ float g_part[2 * NBLK];          // per-block loss partials (nll, count)
__device__ int   g_cs[BB * T1];             // char_seq normalized to int32
__device__ int   g_flag;                    // dtype detector result

// -------------------------------------------------------------------------
// Kernel 0a: detect char_seq dtype.
// Read the buffer as int32 over exactly nelem words (safe for both int32 and
// int64 storage since int64 storage is 2x larger). OR of odd-index words:
//   int64 (LE, values < 2^31): all odd words are zero high-halves  -> OR == 0
//   int32: odd words are random chars in [0,32); ~133k of them all zero is
//          impossible                                              -> OR != 0
// -------------------------------------------------------------------------
__global__ void detect_kernel(const int* __restrict__ src, int nelem) {
    __shared__ int sh[1024];
    int acc = 0;
    for (int i = threadIdx.x; i < nelem; i += 1024)
        if (i & 1) acc |= src[i];
    sh[threadIdx.x] = acc;
    __syncthreads();
    for (int s = 512; s > 0; s >>= 1) {
        if (threadIdx.x < s) sh[threadIdx.x] |= sh[threadIdx.x + s];
        __syncthreads();
    }
    if (threadIdx.x == 0) g_flag = sh[0];
}

// -------------------------------------------------------------------------
// Kernel 0b: convert char_seq -> int32 in g_cs
// -------------------------------------------------------------------------
__global__ void convert_kernel(const void* __restrict__ src) {
    int i = blockIdx.x * blockDim.x + threadIdx.x;
    if (i >= BB * T1) return;
    if (g_flag != 0) {
        g_cs[i] = ((const int*)src)[i];
    } else {
        g_cs[i] = (int)((const long long*)src)[i];
    }
}

// -------------------------------------------------------------------------
// Kernel 1: char table  table[g][c][j] = sum_k emb[c][k] * W_gx[k][j]
// -------------------------------------------------------------------------
__global__ void table_kernel(const float* __restrict__ emb,
                             const float* __restrict__ Wrx,
                             const float* __restrict__ Wzx,
                             const float* __restrict__ Whx) {
    int idx = blockIdx.x * blockDim.x + threadIdx.x;
    if (idx >= 3 * 32 * 64) return;
    int g = idx >> 11;
    int rem = idx & 2047;
    int c = rem >> 6;
    int j = rem & 63;
    const float* W = (g == 0) ? Wrx : ((g == 1) ? Wzx : Whx);
    const float* e = emb + c * HH;
    float acc = 0.f;
#pragma unroll
    for (int k = 0; k < HH; k++) acc = fmaf(e[k], W[k * HH + j], acc);
    g_table[idx] = acc;
}

// -------------------------------------------------------------------------
// Kernel 2: phon part  phonb[g][b][j] = b_gx[j] + b_gh[j] + sum_p phon[b][p]*W_gx[64+p][j]
// -------------------------------------------------------------------------
__global__ void phonb_kernel(const float* __restrict__ phon,
                             const float* __restrict__ Wrx,
                             const float* __restrict__ Wzx,
                             const float* __restrict__ Whx,
                             const float* __restrict__ brx,
                             const float* __restrict__ brh,
                             const float* __restrict__ bzx,
                             const float* __restrict__ bzh,
                             const float* __restrict__ bhx,
                             const float* __restrict__ bhh) {
    int idx = blockIdx.x * blockDim.x + threadIdx.x;
    if (idx >= 3 * BB * 64) return;
    int g = idx / (BB * 64);
    int rem = idx - g * (BB * 64);
    int b = rem >> 6;
    int j = rem & 63;
    const float* W = (g == 0) ? Wrx : ((g == 1) ? Wzx : Whx);
    const float* bx = (g == 0) ? brx : ((g == 1) ? bzx : bhx);
    const float* bh = (g == 0) ? brh : ((g == 1) ? bzh : bhh);
    float acc = bx[j] + bh[j];
    const float* ph = phon + b * PP;
#pragma unroll
    for (int p = 0; p < PP; p++) acc = fmaf(ph[p], W[(HH + p) * HH + j], acc);
    g_phonb[idx] = acc;
}

// -------------------------------------------------------------------------
// Kernel 3: persistent fused GRU recurrence + projection + NLL
//   one block = 16 batch rows, 256 threads, ~98KB dynamic smem
// -------------------------------------------------------------------------
__global__ __launch_bounds__(256, 2)
void gru_kernel(const float* __restrict__ Wrh,
                const float* __restrict__ Wzh,
                const float* __restrict__ Whh,
                const float* __restrict__ Wproj,
                const float* __restrict__ bproj,
                float* __restrict__ out) {
    extern __shared__ float sm[];
    float* sWa  = sm;            // [64][128]: W_rh | W_zh, k-major
    float* sWh  = sm + 8192;     // [64][64]
    float* sWp  = sm + 12288;    // [64][32]
    float* sTab = sm + 14336;    // [3][32][64]
    float* sH   = sm + 20480;    // [16][64]
    float* sRH  = sm + 21504;    // [16][64]  r*h
    float* sZ   = sm + 22528;    // [16][64]  z
    int*   sCS  = (int*)(sm + 23552); // [16][65]
    float* sRed = sm + 24592;    // [16]

    const int tid = threadIdx.x;
    const int b0 = blockIdx.x * BT;

    // cooperative init
    for (int i = tid; i < 8192; i += 256) {
        int k = i >> 7, j = i & 127;
        sWa[i] = (j < 64) ? Wrh[k * 64 + j] : Wzh[k * 64 + (j - 64)];
    }
    for (int i = tid; i < 4096; i += 256) sWh[i] = Whh[i];
    for (int i = tid; i < 2048; i += 256) sWp[i] = Wproj[i];
    for (int i = tid; i < 6144; i += 256) sTab[i] = g_table[i];
    for (int i = tid; i < BT * T1; i += 256) {
        int r = i / T1, t = i - r * T1;
        sCS[i] = g_cs[(b0 + r) * T1 + t];
    }
    for (int i = tid; i < BT * 64; i += 256) sH[i] = 0.f;

    // thread mappings
    const int rq = tid >> 6;         // 0..3 -> rows 4*rq..4*rq+3  (pass A/B)
    const int cg = tid & 63;         // 0..63
    const int j0 = cg << 1;          // 0..126 (pass A col pair over [r|z])
    const int gA = (j0 >= 64) ? 1 : 0;
    const int jjA = j0 & 63;
    const int v  = tid & 31;         // pass C vocab col
    const int rg = tid >> 5;         // 0..7 -> rows 2*rg, 2*rg+1 (pass C)

    float pbA[4][2], pbB[4];
#pragma unroll
    for (int r = 0; r < 4; r++) {
        int base = gA * (BB * 64) + (b0 + 4 * rq + r) * 64 + jjA;
        pbA[r][0] = g_phonb[base];
        pbA[r][1] = g_phonb[base + 1];
        pbB[r] = g_phonb[2 * (BB * 64) + (b0 + 4 * rq + r) * 64 + cg];
    }
    const float bp = bproj[v];
    float nllAcc = 0.f, cntAcc = 0.f;

    __syncthreads();

    for (int t = 0; t < TT; t++) {
        // ---------------- Pass A: r,z gates:  h @ [W_rh|W_zh] -------------
        float acc[4][2];
#pragma unroll
        for (int r = 0; r < 4; r++) { acc[r][0] = 0.f; acc[r][1] = 0.f; }
#pragma unroll
        for (int k4 = 0; k4 < 64; k4 += 4) {
            float hr[4][4];
#pragma unroll
            for (int r = 0; r < 4; r++) {
                float4 hv = *(const float4*)&sH[(4 * rq + r) * 64 + k4];
                hr[r][0] = hv.x; hr[r][1] = hv.y; hr[r][2] = hv.z; hr[r][3] = hv.w;
            }
#pragma unroll
            for (int kk = 0; kk < 4; kk++) {
                float2 w = *(const float2*)&sWa[(k4 + kk) * 128 + j0];
#pragma unroll
                for (int r = 0; r < 4; r++) {
                    acc[r][0] = fmaf(hr[r][kk], w.x, acc[r][0]);
                    acc[r][1] = fmaf(hr[r][kk], w.y, acc[r][1]);
                }
            }
        }
        int cc[4];
#pragma unroll
        for (int r = 0; r < 4; r++) cc[r] = sCS[(4 * rq + r) * T1 + t];
        const float* tg_ = sTab + gA * 2048;
#pragma unroll
        for (int r = 0; r < 4; r++) {
            float2 tv = *(const float2*)&tg_[cc[r] * 64 + jjA];
            float p0 = acc[r][0] + tv.x + pbA[r][0];
            float p1 = acc[r][1] + tv.y + pbA[r][1];
            float g0 = 1.f / (1.f + __expf(-p0));
            float g1 = 1.f / (1.f + __expf(-p1));
            if (gA == 0) {
                float2 ho = *(const float2*)&sH[(4 * rq + r) * 64 + j0];
                float2 o; o.x = g0 * ho.x; o.y = g1 * ho.y;
                *(float2*)&sRH[(4 * rq + r) * 64 + j0] = o;
            } else {
                float2 o; o.x = g0; o.y = g1;
                *(float2*)&sZ[(4 * rq + r) * 64 + jjA] = o;
            }
        }
        __syncthreads();

        // ---------------- Pass B: candidate:  (r*h) @ W_hh ----------------
        float accB[4] = {0.f, 0.f, 0.f, 0.f};
#pragma unroll
        for (int k4 = 0; k4 < 64; k4 += 4) {
            float rr[4][4];
#pragma unroll
            for (int r = 0; r < 4; r++) {
                float4 rv = *(const float4*)&sRH[(4 * rq + r) * 64 + k4];
                rr[r][0] = rv.x; rr[r][1] = rv.y; rr[r][2] = rv.z; rr[r][3] = rv.w;
            }
#pragma unroll
            for (int kk = 0; kk < 4; kk++) {
                float w = sWh[(k4 + kk) * 64 + cg];
#pragma unroll
                for (int r = 0; r < 4; r++)
                    accB[r] = fmaf(rr[r][kk], w, accB[r]);
            }
        }
#pragma unroll
        for (int r = 0; r < 4; r++) {
            float pre = accB[r] + sTab[4096 + cc[r] * 64 + cg] + pbB[r];
            float cv = tanhf(pre);
            int hi = (4 * rq + r) * 64 + cg;
            float z = sZ[hi];
            float ho = sH[hi];
            sH[hi] = fmaf(z, cv - ho, ho);   // (1-z)h + z c
        }
        __syncthreads();

        // ---------------- Pass C: logits + log-softmax NLL ----------------
        float accC[2] = {0.f, 0.f};
#pragma unroll
        for (int k4 = 0; k4 < 64; k4 += 4) {
            float h0[4], h1[4];
            float4 a = *(const float4*)&sH[(2 * rg) * 64 + k4];
            float4 b = *(const float4*)&sH[(2 * rg + 1) * 64 + k4];
            h0[0] = a.x; h0[1] = a.y; h0[2] = a.z; h0[3] = a.w;
            h1[0] = b.x; h1[1] = b.y; h1[2] = b.z; h1[3] = b.w;
#pragma unroll
            for (int kk = 0; kk < 4; kk++) {
                float w = sWp[(k4 + kk) * 32 + v];
                accC[0] = fmaf(h0[kk], w, accC[0]);
                accC[1] = fmaf(h1[kk], w, accC[1]);
            }
        }
#pragma unroll
        for (int r = 0; r < 2; r++) {
            int row = 2 * rg + r;
            float lg = accC[r] + bp;
            out[((long long)(b0 + row) * TT + t) * VV + v] = lg;
            int tgt = sCS[row * T1 + t + 1];
            float m = lg;
#pragma unroll
            for (int o = 16; o > 0; o >>= 1)
                m = fmaxf(m, __shfl_xor_sync(0xffffffffu, m, o));
            float s = __expf(lg - m);
#pragma unroll
            for (int o = 16; o > 0; o >>= 1)
                s += __shfl_xor_sync(0xffffffffu, s, o);
            float lt = __shfl_sync(0xffffffffu, lg, tgt);
            if (v == 0 && tgt != 0) {
                nllAcc += m + __logf(s) - lt;
                cntAcc += 1.f;
            }
        }
        // no sync needed: next pass A only reads sH (stable since pass-B sync)
    }

    // deterministic per-block loss partials
    if (v == 0) { sRed[rg] = nllAcc; sRed[8 + rg] = cntAcc; }
    __syncthreads();
    if (tid == 0) {
        float a = 0.f, c = 0.f;
#pragma unroll
        for (int i = 0; i < 8; i++) { a += sRed[i]; c += sRed[8 + i]; }
        g_part[blockIdx.x] = a;
        g_part[NBLK + blockIdx.x] = c;
    }
}

// -------------------------------------------------------------------------
// Kernel 4: final loss reduction (deterministic tree)
// -------------------------------------------------------------------------
__global__ void loss_kernel(float* __restrict__ out, long long out_size) {
    __shared__ float sa[NBLK], sc[NBLK];
    int tid = threadIdx.x;
    sa[tid] = g_part[tid];
    sc[tid] = g_part[NBLK + tid];
    __syncthreads();
    for (int s = NBLK / 2; s > 0; s >>= 1) {
        if (tid < s) { sa[tid] += sa[tid + s]; sc[tid] += sc[tid + s]; }
        __syncthreads();
    }
    if (tid == 0 && out_size > (long long)BB * TT * VV)
        out[out_size - 1] = sa[0] / fmaxf(sc[0], 1.f);
}

// -------------------------------------------------------------------------
extern "C" void kernel_launch(void* const* d_in, const int* in_sizes, int n_in,
                              void* d_out, int out_size) {
    const float* phon  = (const float*)d_in[0];
    const void*  cs    = d_in[1];                 // int32 or int64 — detected on device
    const float* emb   = (const float*)d_in[2];
    const float* Wrx   = (const float*)d_in[3];
    const float* brx   = (const float*)d_in[4];
    const float* Wrh   = (const float*)d_in[5];
    const float* brh   = (const float*)d_in[6];
    const float* Wzx   = (const float*)d_in[7];
    const float* bzx   = (const float*)d_in[8];
    const float* Wzh   = (const float*)d_in[9];
    const float* bzh   = (const float*)d_in[10];
    const float* Whx   = (const float*)d_in[11];
    const float* bhx   = (const float*)d_in[12];
    const float* Whh   = (const float*)d_in[13];
    const float* bhh   = (const float*)d_in[14];
    const float* Wproj = (const float*)d_in[15];
    const float* bproj = (const float*)d_in[16];
    float* out = (float*)d_out;

    cudaFuncSetAttribute(gru_kernel, cudaFuncAttributeMaxDynamicSharedMemorySize,
                         SMEM_BYTES);

    detect_kernel<<<1, 1024>>>((const int*)cs, BB * T1);
    convert_kernel<<<(BB * T1 + 255) / 256, 256>>>(cs);
    table_kernel<<<24, 256>>>(emb, Wrx, Wzx, Whx);
    phonb_kernel<<<3072, 256>>>(phon, Wrx, Wzx, Whx,
                                brx, brh, bzx, bzh, bhx, bhh);
    gru_kernel<<<NBLK, 256, SMEM_BYTES>>>(Wrh, Wzh, Whh, Wproj, bproj, out);
    loss_kernel<<<1, 256>>>(out, (long long)out_size);
}